// round 2
// baseline (speedup 1.0000x reference)
#include <cuda_runtime.h>
#include <cuda_pipeline.h>
#include <math.h>

#define NTOK 16384
#define DDIM 2048
#define NEXP 64
#define TM   64
#define NBLK (NTOK / TM)      // 256 blocks
#define KC   32
#define NCHUNK (DDIM / KC)    // 64 chunks
#define APAD 36               // padded A row (conflict-free LDS.128, 16B-aligned)
#define ASZ (TM * APAD)       // 2304 floats
#define BSZ (KC * NEXP)       // 2048 floats
#define NOISE_STD (1.0f / 64.0f)

// Deterministic scratch for cross-block reductions (no cudaMalloc allowed).
__device__ float g_part_imp[NBLK][NEXP];
__device__ float g_part_p[NBLK][NEXP];

// ---- packed f32x2 helpers (sm_103a FFMA2 path) ----
__device__ __forceinline__ unsigned long long pack2_dup(float v) {
    unsigned long long r;
    unsigned int u = __float_as_uint(v);
    asm("mov.b64 %0, {%1, %2};" : "=l"(r) : "r"(u), "r"(u));
    return r;
}
__device__ __forceinline__ unsigned long long fma2(unsigned long long a,
                                                   unsigned long long b,
                                                   unsigned long long c) {
    unsigned long long d;
    asm("fma.rn.f32x2 %0, %1, %2, %3;" : "=l"(d) : "l"(a), "l"(b), "l"(c));
    return d;
}
__device__ __forceinline__ void unpack2(unsigned long long v, float& lo, float& hi) {
    unsigned int a, b;
    asm("mov.b64 {%0, %1}, %2;" : "=r"(a), "=r"(b) : "l"(v));
    lo = __uint_as_float(a);
    hi = __uint_as_float(b);
}

// value-then-lower-index "greater" comparator (matches lax.top_k tie order)
__device__ __forceinline__ bool gtv(float a, int ia, float b, int ib) {
    return (a > b) || (a == b && ia < ib);
}

__global__ void __launch_bounds__(128)
router_main(const float* __restrict__ x, const float* __restrict__ W,
            const float* __restrict__ bias_g, const float* __restrict__ noise,
            float* __restrict__ out) {
    // smem: GEMM uses double-buffered As[2][64][36] + Bs[2][32][64] = 8704 f (34.8 KB).
    // Epilogue reuses [0..4223] as Ls[64][66] and [4224..4735] as reduction scratch.
    __shared__ __align__(16) float sm[2 * ASZ + 2 * BSZ];

    const int tid = threadIdx.x;
    const int bm  = blockIdx.x * TM;
    const int gi  = tid >> 3;   // 0..15 -> tokens gi + 16*j
    const int tn  = tid & 7;    // 0..7  -> experts tn*8 .. tn*8+7

    // staging assignment
    const int tokS = tid & 63;         // token row this thread stages
    const int kqS  = (tid >> 6) * 16;  // k-offset half (0 or 16)
    const int eS   = (tid & 15) * 4;   // expert col for W staging
    const int krS  = tid >> 4;         // 0..7 -> W rows krS + 8*i

    const float* xrow = x + (size_t)(bm + tokS) * DDIM;

    auto stage = [&](int buf, int c) {
        float* A = sm + buf * ASZ;
        float* B = sm + 2 * ASZ + buf * BSZ;
        const float* xs = xrow + c * KC + kqS;
        float* ad = A + tokS * APAD + kqS;
#pragma unroll
        for (int i = 0; i < 4; i++)
            __pipeline_memcpy_async(ad + 4 * i, xs + 4 * i, 16);
        const float* ws = W + (size_t)(c * KC + krS) * NEXP + eS;
        float* bd = B + krS * NEXP + eS;
#pragma unroll
        for (int i = 0; i < 4; i++)
            __pipeline_memcpy_async(bd + (size_t)i * 8 * NEXP, ws + (size_t)i * 8 * NEXP, 16);
    };

    // acc[j][q]: token (gi + 16j), expert pair (tn*8+2q, tn*8+2q+1), f32x2-packed over experts
    unsigned long long acc[4][4];
#pragma unroll
    for (int j = 0; j < 4; j++)
#pragma unroll
        for (int q = 0; q < 4; q++) acc[j][q] = 0ull;

    stage(0, 0);
    __pipeline_commit();
    int buf = 0;

    for (int c = 0; c < NCHUNK; ++c) {
        if (c + 1 < NCHUNK) {
            stage(buf ^ 1, c + 1);
            __pipeline_commit();
        }
        __pipeline_wait_prior((c + 1 < NCHUNK) ? 1 : 0);
        __syncthreads();

        const float* A = sm + buf * ASZ;
        const float* B = sm + 2 * ASZ + buf * BSZ;

#pragma unroll 2
        for (int k4 = 0; k4 < KC; k4 += 4) {
            float av[4][4];
#pragma unroll
            for (int j = 0; j < 4; j++) {
                const float4 a4 = *(const float4*)(A + (gi + 16 * j) * APAD + k4);
                av[j][0] = a4.x; av[j][1] = a4.y; av[j][2] = a4.z; av[j][3] = a4.w;
            }
#pragma unroll
            for (int kk = 0; kk < 4; kk++) {
                const ulonglong2 bA = *(const ulonglong2*)(B + (k4 + kk) * NEXP + tn * 8);
                const ulonglong2 bB = *(const ulonglong2*)(B + (k4 + kk) * NEXP + tn * 8 + 4);
                const unsigned long long bq[4] = {bA.x, bA.y, bB.x, bB.y};
#pragma unroll
                for (int j = 0; j < 4; j++) {
                    const unsigned long long ad = pack2_dup(av[j][kk]);
#pragma unroll
                    for (int q = 0; q < 4; q++)
                        acc[j][q] = fma2(ad, bq[q], acc[j][q]);
                }
            }
        }
        __syncthreads();  // all reads of buf done before it is restaged
        buf ^= 1;
    }

    // ---- stage logits (+bias) into Ls[tok][66] (smem reuse; loop ended with a sync)
    float be[8];
#pragma unroll
    for (int q = 0; q < 8; q++) be[q] = __ldg(bias_g + tn * 8 + q);
#pragma unroll
    for (int j = 0; j < 4; j++) {
        const int tok = gi + 16 * j;
#pragma unroll
        for (int q = 0; q < 4; q++) {
            float lo, hi;
            unpack2(acc[j][q], lo, hi);
            *(float2*)(sm + tok * 66 + tn * 8 + 2 * q) =
                make_float2(lo + be[2 * q], hi + be[2 * q + 1]);
        }
    }
    __syncthreads();

    // ---- per-token epilogue: warp wp handles tokens [wp*16, wp*16+16)
    const int lane = tid & 31;
    const int wp   = tid >> 5;
    const int e0   = 2 * lane;
    const int e1   = 2 * lane + 1;

    float imp0 = 0.f, imp1 = 0.f, pa0 = 0.f, pa1 = 0.f;

    for (int tt = 0; tt < 16; ++tt) {
        const int tl = wp * 16 + tt;
        const int t  = bm + tl;
        const float2 L2 = *(const float2*)(sm + tl * 66 + e0);
        const float l0 = L2.x, l1 = L2.y;

        // clean softmax (for importance)
        float mx = fmaxf(l0, l1);
#pragma unroll
        for (int off = 16; off; off >>= 1)
            mx = fmaxf(mx, __shfl_xor_sync(0xffffffffu, mx, off));
        const float s0 = __expf(l0 - mx);
        const float s1 = __expf(l1 - mx);
        float ss = s0 + s1;
#pragma unroll
        for (int off = 16; off; off >>= 1)
            ss += __shfl_xor_sync(0xffffffffu, ss, off);
        const float rs = 1.0f / ss;
        imp0 += s0 * rs;
        imp1 += s1 * rs;

        // noisy logits + warp top-2 (value desc, lower index on ties)
        const float2 nz = *(const float2*)(noise + (size_t)t * NEXP + e0);
        const float n0 = fmaf(NOISE_STD, nz.x, l0);
        const float n1 = fmaf(NOISE_STD, nz.y, l1);
        float v1, v2;
        int i1, i2;
        if (n0 >= n1) { v1 = n0; i1 = e0; v2 = n1; i2 = e1; }
        else          { v1 = n1; i1 = e1; v2 = n0; i2 = e0; }
#pragma unroll
        for (int off = 16; off; off >>= 1) {
            const float ov1 = __shfl_xor_sync(0xffffffffu, v1, off);
            const int   oi1 = __shfl_xor_sync(0xffffffffu, i1, off);
            const float ov2 = __shfl_xor_sync(0xffffffffu, v2, off);
            const int   oi2 = __shfl_xor_sync(0xffffffffu, i2, off);
            if (gtv(ov1, oi1, v1, i1)) {
                if (gtv(v1, i1, ov2, oi2)) { v2 = v1; i2 = i1; }
                else                       { v2 = ov2; i2 = oi2; }
                v1 = ov1; i1 = oi1;
            } else if (gtv(ov1, oi1, v2, i2)) {
                v2 = ov1; i2 = oi1;
            }
        }

        // renormalized top-2 gate values: g1 = 1/(1+exp(v2-v1)), g2 = 1-g1
        const float ee = __expf(v2 - v1);
        const float g1 = 1.0f / (1.0f + ee);
        const float g2 = ee * g1;

        // load-loss probability: p = 1 - Phi((thr - logit)/noise_std) = Phi(-z)
        const float z0 = (v2 - l0) * 64.0f;
        const float z1 = (v2 - l1) * 64.0f;
        pa0 += normcdff(-z0);
        pa1 += normcdff(-z1);

        if (lane == 0) {
            out[2 * t + 0] = g1;
            out[2 * t + 1] = g2;
            out[2 * NTOK + 2 * t + 0] = (float)i1;
            out[2 * NTOK + 2 * t + 1] = (float)i2;
        }
    }

    // ---- deterministic block partials (scratch region does not overlap Ls)
    float* redI = sm + TM * 66;        // [4][64] at 4224
    float* redP = sm + TM * 66 + 256;  // [4][64] at 4480
    redI[wp * 64 + e0] = imp0;
    redI[wp * 64 + e1] = imp1;
    redP[wp * 64 + e0] = pa0;
    redP[wp * 64 + e1] = pa1;
    __syncthreads();
    if (tid < NEXP) {
        g_part_imp[blockIdx.x][tid] =
            redI[tid] + redI[64 + tid] + redI[128 + tid] + redI[192 + tid];
        g_part_p[blockIdx.x][tid] =
            redP[tid] + redP[64 + tid] + redP[128 + tid] + redP[192 + tid];
    }
}

__global__ void __launch_bounds__(1024)
router_reduce(float* __restrict__ out) {
    const int t = threadIdx.x;   // 0..1023
    const int e = t & 63;
    const int r = t >> 6;        // 0..15
    float si = 0.f, sp = 0.f;
#pragma unroll 4
    for (int i = 0; i < NBLK / 16; ++i) {
        const int b = r * (NBLK / 16) + i;
        si += g_part_imp[b][e];
        sp += g_part_p[b][e];
    }
    __shared__ float sa[16][64], sb[16][64];
    sa[r][e] = si;
    sb[r][e] = sp;
    __syncthreads();
    if (t < 64) {
        float a = 0.f, p = 0.f;
#pragma unroll
        for (int r2 = 0; r2 < 16; r2++) { a += sa[r2][t]; p += sb[r2][t]; }
        sa[0][t] = a;
        sb[0][t] = p * (1.0f / NTOK);  // p_mean
    }
    __syncthreads();
    if (t == 0) {
        float ma = 0.f, mp = 0.f;
        for (int i = 0; i < NEXP; i++) { ma += sa[0][i]; mp += sb[0][i]; }
        ma *= (1.0f / NEXP);
        mp *= (1.0f / NEXP);
        float va = 0.f, vp = 0.f;
        for (int i = 0; i < NEXP; i++) {
            const float da = sa[0][i] - ma;
            const float dp = sb[0][i] - mp;
            va += da * da;
            vp += dp * dp;
        }
        va *= (1.0f / (NEXP - 1));  // ddof=1
        vp *= (1.0f / (NEXP - 1));
        const float il = va / ((ma + 1e-8f) * (ma + 1e-8f));
        const float ll = vp / ((mp + 1e-8f) * (mp + 1e-8f));
        out[4 * NTOK] = 0.5f * (il + ll);
    }
}

extern "C" void kernel_launch(void* const* d_in, const int* in_sizes, int n_in,
                              void* d_out, int out_size) {
    const float* x     = (const float*)d_in[0];
    const float* W     = (const float*)d_in[1];
    const float* b     = (const float*)d_in[2];
    const float* noise = (const float*)d_in[3];
    float* out = (float*)d_out;

    router_main<<<NBLK, 128>>>(x, W, b, noise, out);
    router_reduce<<<1, 1024>>>(out);
}

// round 4
// speedup vs baseline: 1.0934x; 1.0934x over previous
#include <cuda_runtime.h>
#include <cuda_pipeline.h>
#include <math.h>
#include <stdint.h>

#define NTOK 16384
#define DDIM 2048
#define NEXP 64
#define TM   128
#define NBLK (NTOK / TM)      // 128 blocks
#define KC   32
#define NCHUNK (DDIM / KC)    // 64 chunks
#define APITCH 36             // A smem pitch (floats) -> conflict-free frag LDS
#define BPITCH 72             // B smem pitch (floats) -> conflict-free frag LDS
#define ASZ (TM * APITCH)     // 4608 f per buffer
#define BSZ (KC * BPITCH)     // 2304 f per buffer
#define NOISE_STD (1.0f / 64.0f)

// smem float offsets
#define OFF_ARAW 0                         // 3 x 4608
#define OFF_BRAW (3 * ASZ)                 // 3 x 2304
#define OFF_BH   (OFF_BRAW + 3 * BSZ)      // 2 x 2304
#define OFF_BL   (OFF_BH + 2 * BSZ)        // 2 x 2304
#define SMEM_F   (OFF_BL + 2 * BSZ)        // 29952 floats
#define SMEM_BYTES (SMEM_F * 4)            // 119808 B

// device scratch (no cudaMalloc allowed)
__device__ float g_part_imp[NBLK][NEXP];
__device__ float g_part_p[NBLK][NEXP];
__device__ int   g_ctr;

__device__ __forceinline__ uint32_t tf32_of(float f) {
    uint32_t u;
    asm("cvt.rna.tf32.f32 %0, %1;" : "=r"(u) : "f"(f));
    return u;
}
__device__ __forceinline__ void mma_tf32(float* c, uint32_t a0, uint32_t a1,
                                         uint32_t a2, uint32_t a3,
                                         uint32_t b0, uint32_t b1) {
    asm volatile(
        "mma.sync.aligned.m16n8k8.row.col.f32.tf32.tf32.f32 "
        "{%0,%1,%2,%3}, {%4,%5,%6,%7}, {%8,%9}, {%0,%1,%2,%3};"
        : "+f"(c[0]), "+f"(c[1]), "+f"(c[2]), "+f"(c[3])
        : "r"(a0), "r"(a1), "r"(a2), "r"(a3), "r"(b0), "r"(b1));
}
__device__ __forceinline__ bool gtv(float a, int ia, float b, int ib) {
    return (a > b) || (a == b && ia < ib);
}

__global__ void __launch_bounds__(128)
router_main(const float* __restrict__ x, const float* __restrict__ W,
            const float* __restrict__ bias_g, const float* __restrict__ noise,
            float* __restrict__ out) {
    extern __shared__ __align__(16) float sm[];

    const int tid  = threadIdx.x;
    const int lane = tid & 31;
    const int w    = tid >> 5;   // warp 0..3 -> C rows [w*32, w*32+32)
    const int g    = lane >> 2;  // 0..7
    const int l4   = lane & 3;   // 0..3
    const int bm   = blockIdx.x * TM;

    const float* xrow = x + (size_t)(bm + tid) * DDIM;

    auto stage = [&](int c) {
        if (c < NCHUNK) {
            // A: this thread's token row, 32 floats
            float* ad = sm + OFF_ARAW + (c % 3) * ASZ + tid * APITCH;
            const float* as = xrow + c * KC;
#pragma unroll
            for (int i = 0; i < 8; i++)
                __pipeline_memcpy_async(ad + 4 * i, as + 4 * i, 16);
            // B: raw W chunk [32k][64n] -> smem [k][BPITCH]
#pragma unroll
            for (int i = 0; i < 4; i++) {
                const int idx = tid + 128 * i;          // 0..511 float4s
                const int k = idx >> 4, c4 = idx & 15;
                __pipeline_memcpy_async(
                    sm + OFF_BRAW + (c % 3) * BSZ + k * BPITCH + 4 * c4,
                    W + (size_t)(c * KC + k) * NEXP + 4 * c4, 16);
            }
        }
        __pipeline_commit();
    };

    float acc[2][8][4];
#pragma unroll
    for (int mi = 0; mi < 2; mi++)
#pragma unroll
        for (int ni = 0; ni < 8; ni++)
#pragma unroll
            for (int r = 0; r < 4; r++) acc[mi][ni][r] = 0.f;

    stage(0); stage(1); stage(2);

    for (int c = 0; c < NCHUNK; ++c) {
        __pipeline_wait_prior(2);   // chunk c landed
        __syncthreads();

        // split B chunk c -> Bh/Bl[c&1] (shared across warps)
        {
            const float* Br = sm + OFF_BRAW + (c % 3) * BSZ;
            float* Bh = sm + OFF_BH + (c & 1) * BSZ;
            float* Bl = sm + OFF_BL + (c & 1) * BSZ;
#pragma unroll
            for (int i = 0; i < 16; i++) {
                const int e = tid + 128 * i;            // 0..2047
                const int k = e >> 6, n = e & 63;
                const float a = Br[k * BPITCH + n];
                const uint32_t hu = tf32_of(a);
                const float hf = __uint_as_float(hu);
                Bh[k * BPITCH + n] = hf;
                Bl[k * BPITCH + n] = __uint_as_float(tf32_of(a - hf));
            }
        }
        __syncthreads();

        const float* Ar = sm + OFF_ARAW + (c % 3) * ASZ;
        const float* Bh = sm + OFF_BH + (c & 1) * BSZ;
        const float* Bl = sm + OFF_BL + (c & 1) * BSZ;

#pragma unroll
        for (int ks = 0; ks < 4; ks++) {
            const int kk = ks * 8 + l4;
            uint32_t ah[2][4], al[2][4];
#pragma unroll
            for (int mi = 0; mi < 2; mi++) {
                const int r0 = w * 32 + mi * 16 + g;
                const float f0 = Ar[r0 * APITCH + kk];
                const float f1 = Ar[(r0 + 8) * APITCH + kk];
                const float f2 = Ar[r0 * APITCH + kk + 4];
                const float f3 = Ar[(r0 + 8) * APITCH + kk + 4];
                ah[mi][0] = tf32_of(f0);
                ah[mi][1] = tf32_of(f1);
                ah[mi][2] = tf32_of(f2);
                ah[mi][3] = tf32_of(f3);
                al[mi][0] = tf32_of(f0 - __uint_as_float(ah[mi][0]));
                al[mi][1] = tf32_of(f1 - __uint_as_float(ah[mi][1]));
                al[mi][2] = tf32_of(f2 - __uint_as_float(ah[mi][2]));
                al[mi][3] = tf32_of(f3 - __uint_as_float(ah[mi][3]));
            }
#pragma unroll
            for (int ni = 0; ni < 8; ni++) {
                const int bo = ni * 8 + g;
                const uint32_t bh0 = __float_as_uint(Bh[(ks * 8 + l4) * BPITCH + bo]);
                const uint32_t bh1 = __float_as_uint(Bh[(ks * 8 + l4 + 4) * BPITCH + bo]);
                const uint32_t bl0 = __float_as_uint(Bl[(ks * 8 + l4) * BPITCH + bo]);
                const uint32_t bl1 = __float_as_uint(Bl[(ks * 8 + l4 + 4) * BPITCH + bo]);
#pragma unroll
                for (int mi = 0; mi < 2; mi++) {
                    mma_tf32(acc[mi][ni], ah[mi][0], ah[mi][1], ah[mi][2], ah[mi][3], bh0, bh1);
                    mma_tf32(acc[mi][ni], ah[mi][0], ah[mi][1], ah[mi][2], ah[mi][3], bl0, bl1);
                    mma_tf32(acc[mi][ni], al[mi][0], al[mi][1], al[mi][2], al[mi][3], bh0, bh1);
                }
            }
        }
        __syncthreads();   // all reads of chunk c buffers done
        stage(c + 3);      // overwrites Araw/Braw[c%3]
    }

    // ---- store C into Ls[128][66] (reuses ARAW region)
    float* Ls = sm;
#pragma unroll
    for (int mi = 0; mi < 2; mi++) {
#pragma unroll
        for (int ni = 0; ni < 8; ni++) {
            const int row = w * 32 + mi * 16 + g;
            const int col = ni * 8 + l4 * 2;
            *(float2*)(Ls + row * 66 + col) = make_float2(acc[mi][ni][0], acc[mi][ni][1]);
            *(float2*)(Ls + (row + 8) * 66 + col) = make_float2(acc[mi][ni][2], acc[mi][ni][3]);
        }
    }
    __syncthreads();

    // ---- per-token epilogue: warp w handles tokens [w*32, w*32+32)
    const int e0 = 2 * lane;
    const int e1 = 2 * lane + 1;
    const float bb0 = __ldg(bias_g + e0);
    const float bb1 = __ldg(bias_g + e1);

    float imp0 = 0.f, imp1 = 0.f, pa0 = 0.f, pa1 = 0.f;

    for (int tt = 0; tt < 32; ++tt) {
        const int tl = w * 32 + tt;
        const int t  = bm + tl;
        const float2 L2 = *(const float2*)(Ls + tl * 66 + e0);
        const float l0 = L2.x + bb0, l1 = L2.y + bb1;

        float mx = fmaxf(l0, l1);
#pragma unroll
        for (int off = 16; off; off >>= 1)
            mx = fmaxf(mx, __shfl_xor_sync(0xffffffffu, mx, off));
        const float s0 = __expf(l0 - mx);
        const float s1 = __expf(l1 - mx);
        float ss = s0 + s1;
#pragma unroll
        for (int off = 16; off; off >>= 1)
            ss += __shfl_xor_sync(0xffffffffu, ss, off);
        const float rs = 1.0f / ss;
        imp0 += s0 * rs;
        imp1 += s1 * rs;

        const float2 nz = *(const float2*)(noise + (size_t)t * NEXP + e0);
        const float n0 = fmaf(NOISE_STD, nz.x, l0);
        const float n1 = fmaf(NOISE_STD, nz.y, l1);
        float v1, v2;
        int i1, i2;
        if (n0 >= n1) { v1 = n0; i1 = e0; v2 = n1; i2 = e1; }
        else          { v1 = n1; i1 = e1; v2 = n0; i2 = e0; }
#pragma unroll
        for (int off = 16; off; off >>= 1) {
            const float ov1 = __shfl_xor_sync(0xffffffffu, v1, off);
            const int   oi1 = __shfl_xor_sync(0xffffffffu, i1, off);
            const float ov2 = __shfl_xor_sync(0xffffffffu, v2, off);
            const int   oi2 = __shfl_xor_sync(0xffffffffu, i2, off);
            if (gtv(ov1, oi1, v1, i1)) {
                if (gtv(v1, i1, ov2, oi2)) { v2 = v1; i2 = i1; }
                else                       { v2 = ov2; i2 = oi2; }
                v1 = ov1; i1 = oi1;
            } else if (gtv(ov1, oi1, v2, i2)) {
                v2 = ov1; i2 = oi1;
            }
        }

        const float ee = __expf(v2 - v1);
        const float g1 = 1.0f / (1.0f + ee);
        const float g2 = ee * g1;

        const float z0 = (v2 - l0) * 64.0f;
        const float z1 = (v2 - l1) * 64.0f;
        pa0 += normcdff(-z0);
        pa1 += normcdff(-z1);

        if (lane == 0) {
            out[2 * t + 0] = g1;
            out[2 * t + 1] = g2;
            out[2 * NTOK + 2 * t + 0] = (float)i1;
            out[2 * NTOK + 2 * t + 1] = (float)i2;
        }
    }

    // ---- block partials (deterministic layout)
    float* redI = sm + 8448;
    float* redP = sm + 8448 + 256;
    redI[w * 64 + e0] = imp0;
    redI[w * 64 + e1] = imp1;
    redP[w * 64 + e0] = pa0;
    redP[w * 64 + e1] = pa1;
    __syncthreads();
    if (tid < NEXP) {
        g_part_imp[blockIdx.x][tid] =
            redI[tid] + redI[64 + tid] + redI[128 + tid] + redI[192 + tid];
        g_part_p[blockIdx.x][tid] =
            redP[tid] + redP[64 + tid] + redP[128 + tid] + redP[192 + tid];
    }

    // ---- last CTA computes aux loss (fixed-order sums -> deterministic)
    __threadfence();
    __shared__ int s_ticket;
    if (tid == 0) s_ticket = atomicAdd(&g_ctr, 1);
    __syncthreads();
    if (s_ticket == NBLK - 1) {
        const int e = tid & 63;
        const int h = tid >> 6;  // 0..1
        float si = 0.f, sp = 0.f;
        for (int b = h * (NBLK / 2); b < (h + 1) * (NBLK / 2); ++b) {
            si += g_part_imp[b][e];
            sp += g_part_p[b][e];
        }
        float* sa = sm;        // reuse smem (post-sync)
        float* sb = sm + 128;
        __syncthreads();
        sa[h * 64 + e] = si;
        sb[h * 64 + e] = sp;
        __syncthreads();
        if (tid == 0) {
            float ma = 0.f, mp = 0.f;
            float va = 0.f, vp = 0.f;
            float ia[NEXP], pa[NEXP];
            for (int i = 0; i < NEXP; i++) {
                ia[i] = sa[i] + sa[64 + i];
                pa[i] = (sb[i] + sb[64 + i]) * (1.0f / NTOK);
                ma += ia[i];
                mp += pa[i];
            }
            ma *= (1.0f / NEXP);
            mp *= (1.0f / NEXP);
            for (int i = 0; i < NEXP; i++) {
                const float da = ia[i] - ma;
                const float dp = pa[i] - mp;
                va += da * da;
                vp += dp * dp;
            }
            va *= (1.0f / (NEXP - 1));  // ddof=1
            vp *= (1.0f / (NEXP - 1));
            const float il = va / ((ma + 1e-8f) * (ma + 1e-8f));
            const float ll = vp / ((mp + 1e-8f) * (mp + 1e-8f));
            g_ctr = 0;  // reset for next graph replay
            out[4 * NTOK] = 0.5f * (il + ll);
        }
    }
}

extern "C" void kernel_launch(void* const* d_in, const int* in_sizes, int n_in,
                              void* d_out, int out_size) {
    const float* x     = (const float*)d_in[0];
    const float* W     = (const float*)d_in[1];
    const float* b     = (const float*)d_in[2];
    const float* noise = (const float*)d_in[3];
    float* out = (float*)d_out;

    cudaFuncSetAttribute(router_main, cudaFuncAttributeMaxDynamicSharedMemorySize, SMEM_BYTES);
    router_main<<<NBLK, 128, SMEM_BYTES>>>(x, W, b, noise, out);
}